// round 3
// baseline (speedup 1.0000x reference)
#include <cuda_runtime.h>
#include <cstdint>

// ============================================================
// BoneLinear: out = x @ (weight + w)^T
//   w block[a,b] = wblk[a,b] @ bone[b] + bone[b]
// Step 1: precompute Weff = weight + w (RN-rounded to tf32) into g_weff
// Step 2: tf32 mma.sync GEMM: [16384,4096] x [4096,4096]^T
//   (tcgen05 unavailable: harness PTX target is plain sm_103)
// ============================================================

#define MDIM 16384
#define NDIM 4096
#define KDIM 4096

#define BM 128
#define BN 256
#define BK 16
#define STAGES 4
#define KT (KDIM / BK)        // 256
#define THREADS 256

// smem: padded pitch of 20 floats (80B) per 16-float row -> conflict-free
#define PITCH_F 20
#define A_STAGE_BYTES (BM * PITCH_F * 4)   // 10240
#define B_STAGE_BYTES (BN * PITCH_F * 4)   // 20480
#define STAGE_BYTES (A_STAGE_BYTES + B_STAGE_BYTES)  // 30720
#define SMEM_TOTAL (STAGES * STAGE_BYTES)            // 122880

__device__ float g_weff[(size_t)NDIM * KDIM];  // 64 MB scratch

// ---------------- helpers ----------------
__device__ __forceinline__ uint32_t smem_u32(const void* p) {
    uint32_t a;
    asm("{ .reg .u64 t; cvta.to.shared.u64 t, %1; cvt.u32.u64 %0, t; }" : "=r"(a) : "l"(p));
    return a;
}

__device__ __forceinline__ void cp16(uint32_t sdst, const float* gsrc) {
    asm volatile("cp.async.cg.shared.global [%0], [%1], 16;" :: "r"(sdst), "l"(gsrc));
}
#define CP_COMMIT() asm volatile("cp.async.commit_group;" ::: "memory")
#define CP_WAIT2()  asm volatile("cp.async.wait_group 2;" ::: "memory")

__device__ __forceinline__ void ldmatrix4(uint32_t* r, uint32_t addr) {
    asm volatile("ldmatrix.sync.aligned.m8n8.x4.shared.b16 {%0,%1,%2,%3}, [%4];"
                 : "=r"(r[0]), "=r"(r[1]), "=r"(r[2]), "=r"(r[3]) : "r"(addr));
}
__device__ __forceinline__ uint32_t lds_b32(uint32_t addr) {
    uint32_t v;
    asm volatile("ld.shared.b32 %0, [%1];" : "=r"(v) : "r"(addr));
    return v;
}
__device__ __forceinline__ uint32_t f2tf32(uint32_t x) {
    uint32_t r;
    asm("cvt.rna.tf32.f32 %0, %1;" : "=r"(r) : "r"(x));
    return r;
}
__device__ __forceinline__ void mma_tf32(float* c, const uint32_t* a, const uint32_t* b) {
    asm volatile(
        "mma.sync.aligned.m16n8k8.row.col.f32.tf32.tf32.f32 "
        "{%0,%1,%2,%3}, {%4,%5,%6,%7}, {%8,%9}, {%0,%1,%2,%3};"
        : "+f"(c[0]), "+f"(c[1]), "+f"(c[2]), "+f"(c[3])
        : "r"(a[0]), "r"(a[1]), "r"(a[2]), "r"(a[3]), "r"(b[0]), "r"(b[1]));
}

// ---------------- precompute: Weff = weight + wblk@bone + bone (tf32 RN) ----------------
__global__ void __launch_bounds__(256, 4)
bone_weff_kernel(const float* __restrict__ weight, const float* __restrict__ bone,
                 float* __restrict__ weff) {
    __shared__ float wblk[64 * 64];
    __shared__ float bb[64 * 64];
    const int b = blockIdx.x, a = blockIdx.y;
    const int t = threadIdx.x;

    for (int idx = t; idx < 4096; idx += 256) {
        int i = idx >> 6, j = idx & 63;
        wblk[idx] = weight[(size_t)(a * 64 + i) * KDIM + b * 64 + j];
        bb[idx] = bone[(size_t)b * 4096 + idx];
    }
    __syncthreads();

    const int i = t >> 2;
    const int j0 = (t & 3) * 16;
    float acc[16];
#pragma unroll
    for (int jj = 0; jj < 16; jj++) acc[jj] = wblk[i * 64 + j0 + jj] + bb[i * 64 + j0 + jj];
    for (int k = 0; k < 64; k++) {
        float wv = wblk[i * 64 + k];
#pragma unroll
        for (int jj = 0; jj < 16; jj++) acc[jj] += wv * bb[k * 64 + j0 + jj];
    }
#pragma unroll
    for (int jj = 0; jj < 16; jj++) {
        float r;
        asm("cvt.rna.tf32.f32 %0, %1;" : "=f"(r) : "f"(acc[jj]));
        weff[(size_t)(a * 64 + i) * KDIM + b * 64 + j0 + jj] = r;
    }
}

// ---------------- main GEMM kernel (sm80-style multistage, tf32 mma.sync) ----------------
__global__ void __launch_bounds__(THREADS, 1)
bone_gemm_kernel(const float* __restrict__ x, const float* __restrict__ weff,
                 float* __restrict__ out) {
    extern __shared__ __align__(128) char smem[];
    const uint32_t sb = smem_u32(smem);

    const int tid = threadIdx.x;
    const int wid = tid >> 5;
    const int lane = tid & 31;
    const int wm = wid & 1;        // 2 warps along M
    const int wn = wid >> 1;       // 4 warps along N
    const int bm = blockIdx.y * BM;
    const int bn = blockIdx.x * BN;

    // ---- cp.async issue for one k-iteration into a stage ----
    auto issue = [&](int kt, int stage) {
        const uint32_t as = sb + stage * STAGE_BYTES;
        const uint32_t bs = as + A_STAGE_BYTES;
        const int kcol = kt * BK;
        // A: 128 rows x 4 chunks of 16B = 512 chunks; 2 per thread
#pragma unroll
        for (int j = 0; j < 2; j++) {
            int idx = tid + j * THREADS;
            int row = idx >> 2, seg = idx & 3;
            cp16(as + row * (PITCH_F * 4) + seg * 16,
                 x + (size_t)(bm + row) * KDIM + kcol + seg * 4);
        }
        // B: 256 rows x 4 chunks = 1024 chunks; 4 per thread
#pragma unroll
        for (int j = 0; j < 4; j++) {
            int idx = tid + j * THREADS;
            int row = idx >> 2, seg = idx & 3;
            cp16(bs + row * (PITCH_F * 4) + seg * 16,
                 weff + (size_t)(bn + row) * KDIM + kcol + seg * 4);
        }
    };

    float c[4][8][4];
#pragma unroll
    for (int mt = 0; mt < 4; mt++)
#pragma unroll
        for (int nt = 0; nt < 8; nt++)
#pragma unroll
            for (int q = 0; q < 4; q++) c[mt][nt][q] = 0.0f;

    // prologue: fill STAGES-1 stages
#pragma unroll
    for (int s = 0; s < STAGES - 1; s++) {
        issue(s, s);
        CP_COMMIT();
    }

    // precomputed per-lane smem offsets
    const uint32_t a_row = (uint32_t)(wm * 64 + (lane & 15));
    const uint32_t a_coff = (uint32_t)((lane >> 4) * 16);          // bytes within k
    const uint32_t b_row = (uint32_t)(wn * 64 + (lane >> 2));      // + nt*8
    const uint32_t b_koff = (uint32_t)((lane & 3) * 4);            // bytes

#pragma unroll 1
    for (int kt = 0; kt < KT; kt++) {
        CP_WAIT2();
        __syncthreads();

        // refill the stage consumed at kt-1
        if (kt + STAGES - 1 < KT) issue(kt + STAGES - 1, (kt + STAGES - 1) % STAGES);
        CP_COMMIT();

        const int stage = kt % STAGES;
        const uint32_t as = sb + stage * STAGE_BYTES;
        const uint32_t bs = as + A_STAGE_BYTES;

#pragma unroll
        for (int ks = 0; ks < BK / 8; ks++) {
            const uint32_t k0b = ks * 32;  // 8 floats
            uint32_t a[4][4];
#pragma unroll
            for (int mt = 0; mt < 4; mt++) {
                ldmatrix4(a[mt], as + (a_row + mt * 16) * (PITCH_F * 4) + k0b + a_coff);
#pragma unroll
                for (int q = 0; q < 4; q++) a[mt][q] = f2tf32(a[mt][q]);
            }
            uint32_t b[8][2];
#pragma unroll
            for (int nt = 0; nt < 8; nt++) {
                uint32_t ba = bs + (b_row + nt * 8) * (PITCH_F * 4) + k0b + b_koff;
                b[nt][0] = lds_b32(ba);
                b[nt][1] = lds_b32(ba + 16);
            }
#pragma unroll
            for (int mt = 0; mt < 4; mt++)
#pragma unroll
                for (int nt = 0; nt < 8; nt++) mma_tf32(c[mt][nt], a[mt], b[nt]);
        }
    }

    // ---- epilogue: fp32 stores ----
    const int er = bm + wm * 64 + (lane >> 2);
    const int ec = bn + wn * 64 + 2 * (lane & 3);
#pragma unroll
    for (int mt = 0; mt < 4; mt++) {
#pragma unroll
        for (int nt = 0; nt < 8; nt++) {
            float* p0 = out + (size_t)(er + mt * 16) * NDIM + ec + nt * 8;
            float* p1 = p0 + 8 * NDIM;
            *reinterpret_cast<float2*>(p0) = make_float2(c[mt][nt][0], c[mt][nt][1]);
            *reinterpret_cast<float2*>(p1) = make_float2(c[mt][nt][2], c[mt][nt][3]);
        }
    }
}

// ---------------- host ----------------
extern "C" void kernel_launch(void* const* d_in, const int* in_sizes, int n_in,
                              void* d_out, int out_size) {
    (void)in_sizes; (void)n_in; (void)out_size;
    const float* x      = (const float*)d_in[0];
    const float* weight = (const float*)d_in[1];
    const float* bone   = (const float*)d_in[2];
    float* out          = (float*)d_out;

    void* weff_ptr = nullptr;
    cudaGetSymbolAddress(&weff_ptr, g_weff);

    cudaFuncSetAttribute((const void*)bone_gemm_kernel,
                         cudaFuncAttributeMaxDynamicSharedMemorySize, SMEM_TOTAL);

    bone_weff_kernel<<<dim3(64, 64), 256>>>(weight, bone, (float*)weff_ptr);
    bone_gemm_kernel<<<dim3(NDIM / BN, MDIM / BM), THREADS, SMEM_TOTAL>>>(
        x, (const float*)weff_ptr, out);
}

// round 5
// speedup vs baseline: 1.0836x; 1.0836x over previous
#include <cuda_runtime.h>
#include <cstdint>

// ============================================================
// BoneLinear: out = x @ (weight + w)^T
// Step 1: precompute Weff = weight + wblk@bone + bone (tf32 RN) into g_weff
// Step 2: tf32 mma.sync GEMM [16384,4096] x [4096,4096]^T
// R3: 2 CTAs/SM (BN=128, warp tile 64x32), BK=32, 3 stages
// ============================================================

#define MDIM 16384
#define NDIM 4096
#define KDIM 4096

#define BM 128
#define BN 128
#define BK 32
#define STAGES 3
#define KT (KDIM / BK)        // 128
#define THREADS 256

// smem: 32 floats (128B) per row padded to 36 floats (144B) -> conflict-free
#define PITCH_F 36
#define PITCH_B (PITCH_F * 4)
#define A_STAGE_BYTES (BM * PITCH_B)   // 18432
#define B_STAGE_BYTES (BN * PITCH_B)   // 18432
#define STAGE_BYTES (A_STAGE_BYTES + B_STAGE_BYTES)  // 36864
#define SMEM_TOTAL (STAGES * STAGE_BYTES)            // 110592 (x2 CTAs = 221184)

__device__ float g_weff[(size_t)NDIM * KDIM];  // 64 MB scratch

// ---------------- helpers ----------------
__device__ __forceinline__ uint32_t smem_u32(const void* p) {
    uint32_t a;
    asm("{ .reg .u64 t; cvta.to.shared.u64 t, %1; cvt.u32.u64 %0, t; }" : "=r"(a) : "l"(p));
    return a;
}
__device__ __forceinline__ void cp16(uint32_t sdst, const float* gsrc) {
    asm volatile("cp.async.cg.shared.global [%0], [%1], 16;" :: "r"(sdst), "l"(gsrc));
}
#define CP_COMMIT() asm volatile("cp.async.commit_group;" ::: "memory")
#define CP_WAIT1()  asm volatile("cp.async.wait_group 1;" ::: "memory")

__device__ __forceinline__ void ldmatrix4(uint32_t* r, uint32_t addr) {
    asm volatile("ldmatrix.sync.aligned.m8n8.x4.shared.b16 {%0,%1,%2,%3}, [%4];"
                 : "=r"(r[0]), "=r"(r[1]), "=r"(r[2]), "=r"(r[3]) : "r"(addr));
}
__device__ __forceinline__ uint32_t lds_b32(uint32_t addr) {
    uint32_t v;
    asm volatile("ld.shared.b32 %0, [%1];" : "=r"(v) : "r"(addr));
    return v;
}
__device__ __forceinline__ uint32_t f2tf32(uint32_t x) {
    uint32_t r;
    asm("cvt.rna.tf32.f32 %0, %1;" : "=r"(r) : "r"(x));
    return r;
}
__device__ __forceinline__ void mma_tf32(float* c, const uint32_t* a, const uint32_t* b) {
    asm volatile(
        "mma.sync.aligned.m16n8k8.row.col.f32.tf32.tf32.f32 "
        "{%0,%1,%2,%3}, {%4,%5,%6,%7}, {%8,%9}, {%0,%1,%2,%3};"
        : "+f"(c[0]), "+f"(c[1]), "+f"(c[2]), "+f"(c[3])
        : "r"(a[0]), "r"(a[1]), "r"(a[2]), "r"(a[3]), "r"(b[0]), "r"(b[1]));
}

// ---------------- precompute: Weff = weight + wblk@bone + bone (tf32 RN) ----------------
__global__ void __launch_bounds__(256, 4)
bone_weff_kernel(const float* __restrict__ weight, const float* __restrict__ bone,
                 float* __restrict__ weff) {
    __shared__ float wblk[64 * 64];
    __shared__ float bb[64 * 64];
    const int b = blockIdx.x, a = blockIdx.y;
    const int t = threadIdx.x;

    for (int idx = t; idx < 4096; idx += 256) {
        int i = idx >> 6, j = idx & 63;
        wblk[idx] = weight[(size_t)(a * 64 + i) * KDIM + b * 64 + j];
        bb[idx] = bone[(size_t)b * 4096 + idx];
    }
    __syncthreads();

    const int i = t >> 2;
    const int j0 = (t & 3) * 16;
    float acc[16];
#pragma unroll
    for (int jj = 0; jj < 16; jj++) acc[jj] = wblk[i * 64 + j0 + jj] + bb[i * 64 + j0 + jj];
    for (int k = 0; k < 64; k++) {
        float wv = wblk[i * 64 + k];
#pragma unroll
        for (int jj = 0; jj < 16; jj++) acc[jj] += wv * bb[k * 64 + j0 + jj];
    }
#pragma unroll
    for (int jj = 0; jj < 16; jj++) {
        float r;
        asm("cvt.rna.tf32.f32 %0, %1;" : "=f"(r) : "f"(acc[jj]));
        weff[(size_t)(a * 64 + i) * KDIM + b * 64 + j0 + jj] = r;
    }
}

// ---------------- main GEMM kernel ----------------
__global__ void __launch_bounds__(THREADS, 2)
bone_gemm_kernel(const float* __restrict__ x, const float* __restrict__ weff,
                 float* __restrict__ out) {
    extern __shared__ __align__(128) char smem[];
    const uint32_t sb = smem_u32(smem);

    const int tid = threadIdx.x;
    const int wid = tid >> 5;
    const int lane = tid & 31;
    const int wm = wid & 1;        // 2 warps along M (64 rows each)
    const int wn = wid >> 1;       // 4 warps along N (32 cols each)
    const int bm = blockIdx.y * BM;
    const int bn = blockIdx.x * BN;

    // ---- cp.async issue for one k-iteration into a stage ----
    auto issue = [&](int kt, int stage) {
        const uint32_t as = sb + stage * STAGE_BYTES;
        const uint32_t bs = as + A_STAGE_BYTES;
        const int kcol = kt * BK;
        // A: 128 rows x 8 chunks of 16B = 1024 chunks; 4 per thread
#pragma unroll
        for (int j = 0; j < 4; j++) {
            int idx = tid + j * THREADS;
            int row = idx >> 3, seg = idx & 7;
            cp16(as + row * PITCH_B + seg * 16,
                 x + (size_t)(bm + row) * KDIM + kcol + seg * 4);
        }
        // B: 128 rows x 8 chunks = 1024 chunks; 4 per thread
#pragma unroll
        for (int j = 0; j < 4; j++) {
            int idx = tid + j * THREADS;
            int row = idx >> 3, seg = idx & 7;
            cp16(bs + row * PITCH_B + seg * 16,
                 weff + (size_t)(bn + row) * KDIM + kcol + seg * 4);
        }
    };

    float c[4][4][4];
#pragma unroll
    for (int mt = 0; mt < 4; mt++)
#pragma unroll
        for (int nt = 0; nt < 4; nt++)
#pragma unroll
            for (int q = 0; q < 4; q++) c[mt][nt][q] = 0.0f;

    // prologue: fill STAGES-1 stages
#pragma unroll
    for (int s = 0; s < STAGES - 1; s++) {
        issue(s, s);
        CP_COMMIT();
    }

    // per-lane smem offsets
    const uint32_t a_row = (uint32_t)(wm * 64 + (lane & 15));
    const uint32_t a_coff = (uint32_t)((lane >> 4) * 16);          // bytes within k
    const uint32_t b_row = (uint32_t)(wn * 32 + (lane >> 2));      // + nt*8
    const uint32_t b_koff = (uint32_t)((lane & 3) * 4);            // bytes

#pragma unroll 1
    for (int kt = 0; kt < KT; kt++) {
        CP_WAIT1();
        __syncthreads();

        if (kt + STAGES - 1 < KT) issue(kt + STAGES - 1, (kt + STAGES - 1) % STAGES);
        CP_COMMIT();

        const int stage = kt % STAGES;
        const uint32_t as = sb + stage * STAGE_BYTES;
        const uint32_t bs = as + A_STAGE_BYTES;

#pragma unroll
        for (int ks = 0; ks < BK / 8; ks++) {
            const uint32_t k0b = ks * 32;  // 8 floats
            uint32_t a[4][4];
#pragma unroll
            for (int mt = 0; mt < 4; mt++) {
                ldmatrix4(a[mt], as + (a_row + mt * 16) * PITCH_B + k0b + a_coff);
#pragma unroll
                for (int q = 0; q < 4; q++) a[mt][q] = f2tf32(a[mt][q]);
            }
            uint32_t b[4][2];
#pragma unroll
            for (int nt = 0; nt < 4; nt++) {
                uint32_t ba = bs + (b_row + nt * 8) * PITCH_B + k0b + b_koff;
                b[nt][0] = lds_b32(ba);
                b[nt][1] = lds_b32(ba + 16);
            }
#pragma unroll
            for (int mt = 0; mt < 4; mt++)
#pragma unroll
                for (int nt = 0; nt < 4; nt++) mma_tf32(c[mt][nt], a[mt], b[nt]);
        }
    }

    // ---- epilogue: fp32 stores ----
    const int er = bm + wm * 64 + (lane >> 2);
    const int ec = bn + wn * 32 + 2 * (lane & 3);
#pragma unroll
    for (int mt = 0; mt < 4; mt++) {
#pragma unroll
        for (int nt = 0; nt < 4; nt++) {
            float* p0 = out + (size_t)(er + mt * 16) * NDIM + ec + nt * 8;
            float* p1 = p0 + 8 * NDIM;
            *reinterpret_cast<float2*>(p0) = make_float2(c[mt][nt][0], c[mt][nt][1]);
            *reinterpret_cast<float2*>(p1) = make_float2(c[mt][nt][2], c[mt][nt][3]);
        }
    }
}

// ---------------- host ----------------
extern "C" void kernel_launch(void* const* d_in, const int* in_sizes, int n_in,
                              void* d_out, int out_size) {
    (void)in_sizes; (void)n_in; (void)out_size;
    const float* x      = (const float*)d_in[0];
    const float* weight = (const float*)d_in[1];
    const float* bone   = (const float*)d_in[2];
    float* out          = (float*)d_out;

    void* weff_ptr = nullptr;
    cudaGetSymbolAddress(&weff_ptr, g_weff);

    cudaFuncSetAttribute((const void*)bone_gemm_kernel,
                         cudaFuncAttributeMaxDynamicSharedMemorySize, SMEM_TOTAL);

    bone_weff_kernel<<<dim3(64, 64), 256>>>(weight, bone, (float*)weff_ptr);
    bone_gemm_kernel<<<dim3(NDIM / BN, MDIM / BM), THREADS, SMEM_TOTAL>>>(
        x, (const float*)weff_ptr, out);
}

// round 6
// speedup vs baseline: 1.2394x; 1.1438x over previous
#include <cuda_runtime.h>
#include <cstdint>

// ============================================================
// BoneLinear: out = x @ (weight + w)^T
// Step 1: precompute Weff = weight + wblk@bone + bone (tf32 RN) into g_weff
// Step 2: tf32 mma.sync GEMM [16384,4096] x [4096,4096]^T
// R6: 128-thr CTAs, warp tile 64x64, 2 CTA/SM, reg double-buffered frags
// ============================================================

#define MDIM 16384
#define NDIM 4096
#define KDIM 4096

#define BM 128
#define BN 128
#define BK 32
#define STAGES 3
#define KT (KDIM / BK)        // 128
#define THREADS 128

// smem: 32 floats (128B) per row padded to 36 floats (144B) -> conflict-free
#define PITCH_F 36
#define PITCH_B (PITCH_F * 4)
#define A_STAGE_BYTES (BM * PITCH_B)   // 18432
#define B_STAGE_BYTES (BN * PITCH_B)   // 18432
#define STAGE_BYTES (A_STAGE_BYTES + B_STAGE_BYTES)  // 36864
#define SMEM_TOTAL (STAGES * STAGE_BYTES)            // 110592 (x2 CTAs = 221184)

__device__ float g_weff[(size_t)NDIM * KDIM];  // 64 MB scratch

// ---------------- helpers ----------------
__device__ __forceinline__ uint32_t smem_u32(const void* p) {
    uint32_t a;
    asm("{ .reg .u64 t; cvta.to.shared.u64 t, %1; cvt.u32.u64 %0, t; }" : "=r"(a) : "l"(p));
    return a;
}
__device__ __forceinline__ void cp16(uint32_t sdst, const float* gsrc) {
    asm volatile("cp.async.cg.shared.global [%0], [%1], 16;" :: "r"(sdst), "l"(gsrc));
}
#define CP_COMMIT() asm volatile("cp.async.commit_group;" ::: "memory")
#define CP_WAIT1()  asm volatile("cp.async.wait_group 1;" ::: "memory")

__device__ __forceinline__ void ldmatrix4(uint32_t* r, uint32_t addr) {
    asm volatile("ldmatrix.sync.aligned.m8n8.x4.shared.b16 {%0,%1,%2,%3}, [%4];"
                 : "=r"(r[0]), "=r"(r[1]), "=r"(r[2]), "=r"(r[3]) : "r"(addr));
}
__device__ __forceinline__ uint32_t lds_b32(uint32_t addr) {
    uint32_t v;
    asm volatile("ld.shared.b32 %0, [%1];" : "=r"(v) : "r"(addr));
    return v;
}
__device__ __forceinline__ uint32_t f2tf32(uint32_t x) {
    uint32_t r;
    asm("cvt.rna.tf32.f32 %0, %1;" : "=r"(r) : "r"(x));
    return r;
}
__device__ __forceinline__ void mma_tf32(float* c, const uint32_t* a, const uint32_t* b) {
    asm volatile(
        "mma.sync.aligned.m16n8k8.row.col.f32.tf32.tf32.f32 "
        "{%0,%1,%2,%3}, {%4,%5,%6,%7}, {%8,%9}, {%0,%1,%2,%3};"
        : "+f"(c[0]), "+f"(c[1]), "+f"(c[2]), "+f"(c[3])
        : "r"(a[0]), "r"(a[1]), "r"(a[2]), "r"(a[3]), "r"(b[0]), "r"(b[1]));
}

// ---------------- precompute: Weff = weight + wblk@bone + bone (tf32 RN) ----------------
__global__ void __launch_bounds__(256, 4)
bone_weff_kernel(const float* __restrict__ weight, const float* __restrict__ bone,
                 float* __restrict__ weff) {
    __shared__ float wblk[64 * 64];
    __shared__ float bb[64 * 64];
    const int b = blockIdx.x, a = blockIdx.y;
    const int t = threadIdx.x;

    for (int idx = t; idx < 4096; idx += 256) {
        int i = idx >> 6, j = idx & 63;
        wblk[idx] = weight[(size_t)(a * 64 + i) * KDIM + b * 64 + j];
        bb[idx] = bone[(size_t)b * 4096 + idx];
    }
    __syncthreads();

    const int i = t >> 2;
    const int j0 = (t & 3) * 16;
    float acc[16];
#pragma unroll
    for (int jj = 0; jj < 16; jj++) acc[jj] = wblk[i * 64 + j0 + jj] + bb[i * 64 + j0 + jj];
    for (int k = 0; k < 64; k++) {
        float wv = wblk[i * 64 + k];
#pragma unroll
        for (int jj = 0; jj < 16; jj++) acc[jj] += wv * bb[k * 64 + j0 + jj];
    }
#pragma unroll
    for (int jj = 0; jj < 16; jj++) {
        float r;
        asm("cvt.rna.tf32.f32 %0, %1;" : "=f"(r) : "f"(acc[jj]));
        weff[(size_t)(a * 64 + i) * KDIM + b * 64 + j0 + jj] = r;
    }
}

// ---------------- main GEMM kernel ----------------
__global__ void __launch_bounds__(THREADS, 2)
bone_gemm_kernel(const float* __restrict__ x, const float* __restrict__ weff,
                 float* __restrict__ out) {
    extern __shared__ __align__(128) char smem[];
    const uint32_t sb = smem_u32(smem);

    const int tid = threadIdx.x;
    const int wid = tid >> 5;
    const int lane = tid & 31;
    const int wm = wid & 1;        // 2 warps along M (64 rows each)
    const int wn = wid >> 1;       // 2 warps along N (64 cols each)
    const int bm = blockIdx.y * BM;
    const int bn = blockIdx.x * BN;

    // ---- cp.async issue for one k-iteration into a stage ----
    auto issue = [&](int kt, int stage) {
        const uint32_t as = sb + stage * STAGE_BYTES;
        const uint32_t bs = as + A_STAGE_BYTES;
        const int kcol = kt * BK;
        // A: 128 rows x 8 chunks of 16B = 1024 chunks; 8 per thread
#pragma unroll
        for (int j = 0; j < 8; j++) {
            int idx = tid + j * THREADS;
            int row = idx >> 3, seg = idx & 7;
            cp16(as + row * PITCH_B + seg * 16,
                 x + (size_t)(bm + row) * KDIM + kcol + seg * 4);
        }
        // B: 128 rows x 8 chunks = 1024 chunks; 8 per thread
#pragma unroll
        for (int j = 0; j < 8; j++) {
            int idx = tid + j * THREADS;
            int row = idx >> 3, seg = idx & 7;
            cp16(bs + row * PITCH_B + seg * 16,
                 weff + (size_t)(bn + row) * KDIM + kcol + seg * 4);
        }
    };

    float c[4][8][4];
#pragma unroll
    for (int mt = 0; mt < 4; mt++)
#pragma unroll
        for (int nt = 0; nt < 8; nt++)
#pragma unroll
            for (int q = 0; q < 4; q++) c[mt][nt][q] = 0.0f;

    // prologue: fill STAGES-1 stages
#pragma unroll
    for (int s = 0; s < STAGES - 1; s++) {
        issue(s, s);
        CP_COMMIT();
    }

    // per-lane smem offsets
    const uint32_t a_row = (uint32_t)(wm * 64 + (lane & 15));
    const uint32_t a_coff = (uint32_t)((lane >> 4) * 16);          // bytes within k
    const uint32_t b_row = (uint32_t)(wn * 64 + (lane >> 2));      // + nt*8
    const uint32_t b_koff = (uint32_t)((lane & 3) * 4);            // bytes

    // double-buffered fragments
    uint32_t af[2][4][4];
    uint32_t bf[2][8][2];

    auto load_frags = [&](uint32_t as, uint32_t bs, int ks, int buf) {
        const uint32_t k0b = (uint32_t)(ks * 32);  // 8 floats
#pragma unroll
        for (int mt = 0; mt < 4; mt++) {
            ldmatrix4(af[buf][mt], as + (a_row + mt * 16) * PITCH_B + k0b + a_coff);
#pragma unroll
            for (int q = 0; q < 4; q++) af[buf][mt][q] = f2tf32(af[buf][mt][q]);
        }
#pragma unroll
        for (int nt = 0; nt < 8; nt++) {
            uint32_t ba = bs + (b_row + nt * 8) * PITCH_B + k0b + b_koff;
            bf[buf][nt][0] = lds_b32(ba);
            bf[buf][nt][1] = lds_b32(ba + 16);
        }
    };

#pragma unroll 1
    for (int kt = 0; kt < KT; kt++) {
        CP_WAIT1();
        __syncthreads();

        const int stage = kt % STAGES;
        const uint32_t as = sb + stage * STAGE_BYTES;
        const uint32_t bs = as + A_STAGE_BYTES;

        // prefetch first fragment slice, then issue next-stage cp.async
        load_frags(as, bs, 0, 0);
        if (kt + STAGES - 1 < KT) issue(kt + STAGES - 1, (kt + STAGES - 1) % STAGES);
        CP_COMMIT();

#pragma unroll
        for (int ks = 0; ks < BK / 8; ks++) {
            const int cur = ks & 1;
            if (ks < BK / 8 - 1) load_frags(as, bs, ks + 1, cur ^ 1);
#pragma unroll
            for (int mt = 0; mt < 4; mt++)
#pragma unroll
                for (int nt = 0; nt < 8; nt++)
                    mma_tf32(c[mt][nt], af[cur][mt], bf[cur][nt]);
        }
    }

    // ---- epilogue: fp32 stores ----
    const int er = bm + wm * 64 + (lane >> 2);
    const int ec = bn + wn * 64 + 2 * (lane & 3);
#pragma unroll
    for (int mt = 0; mt < 4; mt++) {
#pragma unroll
        for (int nt = 0; nt < 8; nt++) {
            float* p0 = out + (size_t)(er + mt * 16) * NDIM + ec + nt * 8;
            float* p1 = p0 + 8 * NDIM;
            *reinterpret_cast<float2*>(p0) = make_float2(c[mt][nt][0], c[mt][nt][1]);
            *reinterpret_cast<float2*>(p1) = make_float2(c[mt][nt][2], c[mt][nt][3]);
        }
    }
}

// ---------------- host ----------------
extern "C" void kernel_launch(void* const* d_in, const int* in_sizes, int n_in,
                              void* d_out, int out_size) {
    (void)in_sizes; (void)n_in; (void)out_size;
    const float* x      = (const float*)d_in[0];
    const float* weight = (const float*)d_in[1];
    const float* bone   = (const float*)d_in[2];
    float* out          = (float*)d_out;

    void* weff_ptr = nullptr;
    cudaGetSymbolAddress(&weff_ptr, g_weff);

    cudaFuncSetAttribute((const void*)bone_gemm_kernel,
                         cudaFuncAttributeMaxDynamicSharedMemorySize, SMEM_TOTAL);

    bone_weff_kernel<<<dim3(64, 64), 256>>>(weight, bone, (float*)weff_ptr);
    bone_gemm_kernel<<<dim3(NDIM / BN, MDIM / BM), THREADS, SMEM_TOTAL>>>(
        x, (const float*)weff_ptr, out);
}

// round 7
// speedup vs baseline: 1.4063x; 1.1346x over previous
#include <cuda_runtime.h>
#include <cstdint>

// ============================================================
// BoneLinear: out = x @ (weight + w)^T
// Step 1a: precompute Weff = weight + wblk@bone + bone (tf32 RN) into g_weff
// Step 1b: pre-round x to tf32 into g_xtf (removes per-ks cvts from mainloop)
// Step 2: tf32 mma.sync GEMM [16384,4096] x [4096,4096]^T
// R7: no in-loop cvt, cp.async issue interleaved into ks loop
// ============================================================

#define MDIM 16384
#define NDIM 4096
#define KDIM 4096

#define BM 128
#define BN 128
#define BK 32
#define STAGES 3
#define KT (KDIM / BK)        // 128
#define THREADS 128

// smem: 32 floats (128B) per row padded to 36 floats (144B) -> conflict-free
#define PITCH_F 36
#define PITCH_B (PITCH_F * 4)
#define A_STAGE_BYTES (BM * PITCH_B)   // 18432
#define B_STAGE_BYTES (BN * PITCH_B)   // 18432
#define STAGE_BYTES (A_STAGE_BYTES + B_STAGE_BYTES)  // 36864
#define SMEM_TOTAL (STAGES * STAGE_BYTES)            // 110592 (x2 CTAs = 221184)

__device__ float g_weff[(size_t)NDIM * KDIM];        // 64 MB
__device__ float g_xtf[(size_t)MDIM * KDIM];         // 256 MB (tf32-rounded x)

// ---------------- helpers ----------------
__device__ __forceinline__ uint32_t smem_u32(const void* p) {
    uint32_t a;
    asm("{ .reg .u64 t; cvta.to.shared.u64 t, %1; cvt.u32.u64 %0, t; }" : "=r"(a) : "l"(p));
    return a;
}
__device__ __forceinline__ void cp16(uint32_t sdst, const float* gsrc) {
    asm volatile("cp.async.cg.shared.global [%0], [%1], 16;" :: "r"(sdst), "l"(gsrc));
}
#define CP_COMMIT() asm volatile("cp.async.commit_group;" ::: "memory")
#define CP_WAIT1()  asm volatile("cp.async.wait_group 1;" ::: "memory")

__device__ __forceinline__ void ldmatrix4(uint32_t* r, uint32_t addr) {
    asm volatile("ldmatrix.sync.aligned.m8n8.x4.shared.b16 {%0,%1,%2,%3}, [%4];"
                 : "=r"(r[0]), "=r"(r[1]), "=r"(r[2]), "=r"(r[3]) : "r"(addr));
}
__device__ __forceinline__ uint32_t lds_b32(uint32_t addr) {
    uint32_t v;
    asm volatile("ld.shared.b32 %0, [%1];" : "=r"(v) : "r"(addr));
    return v;
}
__device__ __forceinline__ void mma_tf32(float* c, const uint32_t* a, const uint32_t* b) {
    asm volatile(
        "mma.sync.aligned.m16n8k8.row.col.f32.tf32.tf32.f32 "
        "{%0,%1,%2,%3}, {%4,%5,%6,%7}, {%8,%9}, {%0,%1,%2,%3};"
        : "+f"(c[0]), "+f"(c[1]), "+f"(c[2]), "+f"(c[3])
        : "r"(a[0]), "r"(a[1]), "r"(a[2]), "r"(a[3]), "r"(b[0]), "r"(b[1]));
}

// ---------------- precompute 1a: Weff = weight + wblk@bone + bone (tf32 RN) ----------------
__global__ void __launch_bounds__(256, 4)
bone_weff_kernel(const float* __restrict__ weight, const float* __restrict__ bone,
                 float* __restrict__ weff) {
    __shared__ float wblk[64 * 64];
    __shared__ float bb[64 * 64];
    const int b = blockIdx.x, a = blockIdx.y;
    const int t = threadIdx.x;

    for (int idx = t; idx < 4096; idx += 256) {
        int i = idx >> 6, j = idx & 63;
        wblk[idx] = weight[(size_t)(a * 64 + i) * KDIM + b * 64 + j];
        bb[idx] = bone[(size_t)b * 4096 + idx];
    }
    __syncthreads();

    const int i = t >> 2;
    const int j0 = (t & 3) * 16;
    float acc[16];
#pragma unroll
    for (int jj = 0; jj < 16; jj++) acc[jj] = wblk[i * 64 + j0 + jj] + bb[i * 64 + j0 + jj];
    for (int k = 0; k < 64; k++) {
        float wv = wblk[i * 64 + k];
#pragma unroll
        for (int jj = 0; jj < 16; jj++) acc[jj] += wv * bb[k * 64 + j0 + jj];
    }
#pragma unroll
    for (int jj = 0; jj < 16; jj++) {
        float r;
        asm("cvt.rna.tf32.f32 %0, %1;" : "=f"(r) : "f"(acc[jj]));
        weff[(size_t)(a * 64 + i) * KDIM + b * 64 + j0 + jj] = r;
    }
}

// ---------------- precompute 1b: x -> tf32-rounded copy ----------------
__global__ void __launch_bounds__(512, 4)
bone_xcvt_kernel(const float* __restrict__ x, float* __restrict__ xtf) {
    size_t i = ((size_t)blockIdx.x * 512 + threadIdx.x) * 4;
    float4 v = *reinterpret_cast<const float4*>(x + i);
    float4 r;
    asm("cvt.rna.tf32.f32 %0, %1;" : "=f"(r.x) : "f"(v.x));
    asm("cvt.rna.tf32.f32 %0, %1;" : "=f"(r.y) : "f"(v.y));
    asm("cvt.rna.tf32.f32 %0, %1;" : "=f"(r.z) : "f"(v.z));
    asm("cvt.rna.tf32.f32 %0, %1;" : "=f"(r.w) : "f"(v.w));
    *reinterpret_cast<float4*>(xtf + i) = r;
}

// ---------------- main GEMM kernel ----------------
__global__ void __launch_bounds__(THREADS, 2)
bone_gemm_kernel(const float* __restrict__ xtf, const float* __restrict__ weff,
                 float* __restrict__ out) {
    extern __shared__ __align__(128) char smem[];
    const uint32_t sb = smem_u32(smem);

    const int tid = threadIdx.x;
    const int wid = tid >> 5;
    const int lane = tid & 31;
    const int wm = wid & 1;        // 2 warps along M (64 rows each)
    const int wn = wid >> 1;       // 2 warps along N (64 cols each)
    const int bm = blockIdx.y * BM;
    const int bn = blockIdx.x * BN;

    // ---- cp.async: one quarter (2 A chunks + 2 B chunks per thread) ----
    auto issue_part = [&](int kt, int stage, int part) {
        const uint32_t as = sb + stage * STAGE_BYTES;
        const uint32_t bs = as + A_STAGE_BYTES;
        const int kcol = kt * BK;
#pragma unroll
        for (int j = part * 2; j < part * 2 + 2; j++) {
            int idx = tid + j * THREADS;
            int row = idx >> 3, seg = idx & 7;
            cp16(as + row * PITCH_B + seg * 16,
                 xtf + (size_t)(bm + row) * KDIM + kcol + seg * 4);
            cp16(bs + row * PITCH_B + seg * 16,
                 weff + (size_t)(bn + row) * KDIM + kcol + seg * 4);
        }
    };

    float c[4][8][4];
#pragma unroll
    for (int mt = 0; mt < 4; mt++)
#pragma unroll
        for (int nt = 0; nt < 8; nt++)
#pragma unroll
            for (int q = 0; q < 4; q++) c[mt][nt][q] = 0.0f;

    // prologue: fill STAGES-1 stages
#pragma unroll
    for (int s = 0; s < STAGES - 1; s++) {
#pragma unroll
        for (int p = 0; p < 4; p++) issue_part(s, s, p);
        CP_COMMIT();
    }

    // per-lane smem offsets
    const uint32_t a_row = (uint32_t)(wm * 64 + (lane & 15));
    const uint32_t a_coff = (uint32_t)((lane >> 4) * 16);          // bytes within k
    const uint32_t b_row = (uint32_t)(wn * 64 + (lane >> 2));      // + nt*8
    const uint32_t b_koff = (uint32_t)((lane & 3) * 4);            // bytes

    // double-buffered fragments
    uint32_t af[2][4][4];
    uint32_t bf[2][8][2];

    auto load_frags = [&](uint32_t as, uint32_t bs, int ks, int buf) {
        const uint32_t k0b = (uint32_t)(ks * 32);  // 8 floats
#pragma unroll
        for (int mt = 0; mt < 4; mt++)
            ldmatrix4(af[buf][mt], as + (a_row + mt * 16) * PITCH_B + k0b + a_coff);
#pragma unroll
        for (int nt = 0; nt < 8; nt++) {
            uint32_t ba = bs + (b_row + nt * 8) * PITCH_B + k0b + b_koff;
            bf[buf][nt][0] = lds_b32(ba);
            bf[buf][nt][1] = lds_b32(ba + 16);
        }
    };

#pragma unroll 1
    for (int kt = 0; kt < KT; kt++) {
        CP_WAIT1();
        __syncthreads();

        const int stage = kt % STAGES;
        const uint32_t as = sb + stage * STAGE_BYTES;
        const uint32_t bs = as + A_STAGE_BYTES;

        load_frags(as, bs, 0, 0);

        const int nkt = kt + STAGES - 1;
        const int nstage = nkt % STAGES;
        const bool do_issue = nkt < KT;

#pragma unroll
        for (int ks = 0; ks < BK / 8; ks++) {
            const int cur = ks & 1;
            if (ks < BK / 8 - 1) load_frags(as, bs, ks + 1, cur ^ 1);
#pragma unroll
            for (int mt = 0; mt < 4; mt++)
#pragma unroll
                for (int nt = 0; nt < 8; nt++)
                    mma_tf32(c[mt][nt], af[cur][mt], bf[cur][nt]);
            if (do_issue) issue_part(nkt, nstage, ks);
        }
        CP_COMMIT();
    }

    // ---- epilogue: fp32 stores ----
    const int er = bm + wm * 64 + (lane >> 2);
    const int ec = bn + wn * 64 + 2 * (lane & 3);
#pragma unroll
    for (int mt = 0; mt < 4; mt++) {
#pragma unroll
        for (int nt = 0; nt < 8; nt++) {
            float* p0 = out + (size_t)(er + mt * 16) * NDIM + ec + nt * 8;
            float* p1 = p0 + 8 * NDIM;
            *reinterpret_cast<float2*>(p0) = make_float2(c[mt][nt][0], c[mt][nt][1]);
            *reinterpret_cast<float2*>(p1) = make_float2(c[mt][nt][2], c[mt][nt][3]);
        }
    }
}

// ---------------- host ----------------
extern "C" void kernel_launch(void* const* d_in, const int* in_sizes, int n_in,
                              void* d_out, int out_size) {
    (void)in_sizes; (void)n_in; (void)out_size;
    const float* x      = (const float*)d_in[0];
    const float* weight = (const float*)d_in[1];
    const float* bone   = (const float*)d_in[2];
    float* out          = (float*)d_out;

    void* weff_ptr = nullptr;
    cudaGetSymbolAddress(&weff_ptr, g_weff);
    void* xtf_ptr = nullptr;
    cudaGetSymbolAddress(&xtf_ptr, g_xtf);

    cudaFuncSetAttribute((const void*)bone_gemm_kernel,
                         cudaFuncAttributeMaxDynamicSharedMemorySize, SMEM_TOTAL);

    bone_weff_kernel<<<dim3(64, 64), 256>>>(weight, bone, (float*)weff_ptr);
    bone_xcvt_kernel<<<(int)(((size_t)MDIM * KDIM) / (512 * 4)), 512>>>(x, (float*)xtf_ptr);
    bone_gemm_kernel<<<dim3(NDIM / BN, MDIM / BM), THREADS, SMEM_TOTAL>>>(
        (const float*)xtf_ptr, (const float*)weff_ptr, out);
}

// round 8
// speedup vs baseline: 1.4822x; 1.0540x over previous
#include <cuda_runtime.h>
#include <cstdint>

// ============================================================
// BoneLinear: out = x @ (weight + w)^T
// Step 1: precompute Weff = weight + wblk@bone + bone (tf32 RNA) into g_weff
//         (bank-conflict-free: transposed+padded W, float4 bone reads)
// Step 2: tf32 mma.sync GEMM [16384,4096] x [4096,4096]^T
//         A = raw fp32 x (HW tf32 truncation), B = RNA-rounded Weff
// ============================================================

#define MDIM 16384
#define NDIM 4096
#define KDIM 4096

#define BM 128
#define BN 128
#define BK 32
#define STAGES 3
#define KT (KDIM / BK)        // 128
#define THREADS 128

// smem: 32 floats (128B) per row padded to 36 floats (144B) -> conflict-free
#define PITCH_F 36
#define PITCH_B (PITCH_F * 4)
#define A_STAGE_BYTES (BM * PITCH_B)   // 18432
#define B_STAGE_BYTES (BN * PITCH_B)   // 18432
#define STAGE_BYTES (A_STAGE_BYTES + B_STAGE_BYTES)  // 36864
#define SMEM_TOTAL (STAGES * STAGE_BYTES)            // 110592 (x2 CTAs = 221184)

__device__ float g_weff[(size_t)NDIM * KDIM];        // 64 MB

// ---------------- helpers ----------------
__device__ __forceinline__ uint32_t smem_u32(const void* p) {
    uint32_t a;
    asm("{ .reg .u64 t; cvta.to.shared.u64 t, %1; cvt.u32.u64 %0, t; }" : "=r"(a) : "l"(p));
    return a;
}
__device__ __forceinline__ void cp16(uint32_t sdst, const float* gsrc) {
    asm volatile("cp.async.cg.shared.global [%0], [%1], 16;" :: "r"(sdst), "l"(gsrc));
}
#define CP_COMMIT() asm volatile("cp.async.commit_group;" ::: "memory")
#define CP_WAIT1()  asm volatile("cp.async.wait_group 1;" ::: "memory")

__device__ __forceinline__ void ldmatrix4(uint32_t* r, uint32_t addr) {
    asm volatile("ldmatrix.sync.aligned.m8n8.x4.shared.b16 {%0,%1,%2,%3}, [%4];"
                 : "=r"(r[0]), "=r"(r[1]), "=r"(r[2]), "=r"(r[3]) : "r"(addr));
}
__device__ __forceinline__ uint32_t lds_b32(uint32_t addr) {
    uint32_t v;
    asm volatile("ld.shared.b32 %0, [%1];" : "=r"(v) : "r"(addr));
    return v;
}
__device__ __forceinline__ void mma_tf32(float* c, const uint32_t* a, const uint32_t* b) {
    asm volatile(
        "mma.sync.aligned.m16n8k8.row.col.f32.tf32.tf32.f32 "
        "{%0,%1,%2,%3}, {%4,%5,%6,%7}, {%8,%9}, {%0,%1,%2,%3};"
        : "+f"(c[0]), "+f"(c[1]), "+f"(c[2]), "+f"(c[3])
        : "r"(a[0]), "r"(a[1]), "r"(a[2]), "r"(a[3]), "r"(b[0]), "r"(b[1]));
}

// ---------------- precompute: Weff = weight + wblk@bone + bone (tf32 RNA) ----------------
__global__ void __launch_bounds__(256, 4)
bone_weff_kernel(const float* __restrict__ weight, const float* __restrict__ bone,
                 float* __restrict__ weff) {
    __shared__ float wT[64 * 65];   // wT[j*65+i] = W[i][j], pad 65 -> conflict-free
    __shared__ float bb[64 * 64];
    const int b = blockIdx.x, a = blockIdx.y;
    const int t = threadIdx.x;

    for (int idx = t; idx < 4096; idx += 256) {
        int i = idx >> 6, j = idx & 63;
        wT[j * 65 + i] = weight[(size_t)(a * 64 + i) * KDIM + b * 64 + j];
        bb[idx] = bone[(size_t)b * 4096 + idx];
    }
    __syncthreads();

    const int i = t >> 2;           // output row within block
    const int q = t & 3;            // quarter: cols q*16 .. q*16+15
    const int j0 = q * 16;

    float acc[16];
#pragma unroll
    for (int jj = 0; jj < 16; jj++)
        acc[jj] = wT[(j0 + jj) * 65 + i] + bb[i * 64 + j0 + jj];

    const float4* bb4 = reinterpret_cast<const float4*>(bb);
#pragma unroll 4
    for (int k = 0; k < 64; k++) {
        const float wv = wT[k * 65 + i];                 // 8 distinct banks/warp
        const float4 b0 = bb4[k * 16 + q * 4 + 0];       // broadcast LDS.128
        const float4 b1 = bb4[k * 16 + q * 4 + 1];
        const float4 b2 = bb4[k * 16 + q * 4 + 2];
        const float4 b3 = bb4[k * 16 + q * 4 + 3];
        acc[0] += wv * b0.x;  acc[1] += wv * b0.y;  acc[2] += wv * b0.z;  acc[3] += wv * b0.w;
        acc[4] += wv * b1.x;  acc[5] += wv * b1.y;  acc[6] += wv * b1.z;  acc[7] += wv * b1.w;
        acc[8] += wv * b2.x;  acc[9] += wv * b2.y;  acc[10] += wv * b2.z; acc[11] += wv * b2.w;
        acc[12] += wv * b3.x; acc[13] += wv * b3.y; acc[14] += wv * b3.z; acc[15] += wv * b3.w;
    }

#pragma unroll
    for (int jj = 0; jj < 16; jj++)
        asm("cvt.rna.tf32.f32 %0, %1;" : "=f"(acc[jj]) : "f"(acc[jj]));

    float* orow = weff + (size_t)(a * 64 + i) * KDIM + b * 64 + j0;
#pragma unroll
    for (int v = 0; v < 4; v++)
        *reinterpret_cast<float4*>(orow + v * 4) =
            make_float4(acc[v * 4], acc[v * 4 + 1], acc[v * 4 + 2], acc[v * 4 + 3]);
}

// ---------------- main GEMM kernel ----------------
__global__ void __launch_bounds__(THREADS, 2)
bone_gemm_kernel(const float* __restrict__ x, const float* __restrict__ weff,
                 float* __restrict__ out) {
    extern __shared__ __align__(128) char smem[];
    const uint32_t sb = smem_u32(smem);

    const int tid = threadIdx.x;
    const int wid = tid >> 5;
    const int lane = tid & 31;
    const int wm = wid & 1;        // 2 warps along M (64 rows each)
    const int wn = wid >> 1;       // 2 warps along N (64 cols each)
    const int bm = blockIdx.y * BM;
    const int bn = blockIdx.x * BN;

    // ---- cp.async: one quarter (2 A chunks + 2 B chunks per thread) ----
    auto issue_part = [&](int kt, int stage, int part) {
        const uint32_t as = sb + stage * STAGE_BYTES;
        const uint32_t bs = as + A_STAGE_BYTES;
        const int kcol = kt * BK;
#pragma unroll
        for (int j = part * 2; j < part * 2 + 2; j++) {
            int idx = tid + j * THREADS;
            int row = idx >> 3, seg = idx & 7;
            cp16(as + row * PITCH_B + seg * 16,
                 x + (size_t)(bm + row) * KDIM + kcol + seg * 4);
            cp16(bs + row * PITCH_B + seg * 16,
                 weff + (size_t)(bn + row) * KDIM + kcol + seg * 4);
        }
    };

    float c[4][8][4];
#pragma unroll
    for (int mt = 0; mt < 4; mt++)
#pragma unroll
        for (int nt = 0; nt < 8; nt++)
#pragma unroll
            for (int q = 0; q < 4; q++) c[mt][nt][q] = 0.0f;

    // prologue: fill STAGES-1 stages
#pragma unroll
    for (int s = 0; s < STAGES - 1; s++) {
#pragma unroll
        for (int p = 0; p < 4; p++) issue_part(s, s, p);
        CP_COMMIT();
    }

    // per-lane smem offsets
    const uint32_t a_row = (uint32_t)(wm * 64 + (lane & 15));
    const uint32_t a_coff = (uint32_t)((lane >> 4) * 16);          // bytes within k
    const uint32_t b_row = (uint32_t)(wn * 64 + (lane >> 2));      // + nt*8
    const uint32_t b_koff = (uint32_t)((lane & 3) * 4);            // bytes

    // double-buffered fragments
    uint32_t af[2][4][4];
    uint32_t bf[2][8][2];

    auto load_frags = [&](uint32_t as, uint32_t bs, int ks, int buf) {
        const uint32_t k0b = (uint32_t)(ks * 32);  // 8 floats
#pragma unroll
        for (int mt = 0; mt < 4; mt++)
            ldmatrix4(af[buf][mt], as + (a_row + mt * 16) * PITCH_B + k0b + a_coff);
#pragma unroll
        for (int nt = 0; nt < 8; nt++) {
            uint32_t ba = bs + (b_row + nt * 8) * PITCH_B + k0b + b_koff;
            bf[buf][nt][0] = lds_b32(ba);
            bf[buf][nt][1] = lds_b32(ba + 16);
        }
    };

#pragma unroll 1
    for (int kt = 0; kt < KT; kt++) {
        CP_WAIT1();
        __syncthreads();

        const int stage = kt % STAGES;
        const uint32_t as = sb + stage * STAGE_BYTES;
        const uint32_t bs = as + A_STAGE_BYTES;

        load_frags(as, bs, 0, 0);

        const int nkt = kt + STAGES - 1;
        const int nstage = nkt % STAGES;
        const bool do_issue = nkt < KT;

#pragma unroll
        for (int ks = 0; ks < BK / 8; ks++) {
            const int cur = ks & 1;
            if (ks < BK / 8 - 1) load_frags(as, bs, ks + 1, cur ^ 1);
#pragma unroll
            for (int mt = 0; mt < 4; mt++)
#pragma unroll
                for (int nt = 0; nt < 8; nt++)
                    mma_tf32(c[mt][nt], af[cur][mt], bf[cur][nt]);
            if (do_issue) issue_part(nkt, nstage, ks);
        }
        CP_COMMIT();
    }

    // ---- epilogue: fp32 stores ----
    const int er = bm + wm * 64 + (lane >> 2);
    const int ec = bn + wn * 64 + 2 * (lane & 3);
#pragma unroll
    for (int mt = 0; mt < 4; mt++) {
#pragma unroll
        for (int nt = 0; nt < 8; nt++) {
            float* p0 = out + (size_t)(er + mt * 16) * NDIM + ec + nt * 8;
            float* p1 = p0 + 8 * NDIM;
            *reinterpret_cast<float2*>(p0) = make_float2(c[mt][nt][0], c[mt][nt][1]);
            *reinterpret_cast<float2*>(p1) = make_float2(c[mt][nt][2], c[mt][nt][3]);
        }
    }
}

// ---------------- host ----------------
extern "C" void kernel_launch(void* const* d_in, const int* in_sizes, int n_in,
                              void* d_out, int out_size) {
    (void)in_sizes; (void)n_in; (void)out_size;
    const float* x      = (const float*)d_in[0];
    const float* weight = (const float*)d_in[1];
    const float* bone   = (const float*)d_in[2];
    float* out          = (float*)d_out;

    void* weff_ptr = nullptr;
    cudaGetSymbolAddress(&weff_ptr, g_weff);

    cudaFuncSetAttribute((const void*)bone_gemm_kernel,
                         cudaFuncAttributeMaxDynamicSharedMemorySize, SMEM_TOTAL);

    bone_weff_kernel<<<dim3(64, 64), 256>>>(weight, bone, (float*)weff_ptr);
    bone_gemm_kernel<<<dim3(NDIM / BN, MDIM / BM), THREADS, SMEM_TOTAL>>>(
        x, (const float*)weff_ptr, out);
}

// round 9
// speedup vs baseline: 1.7180x; 1.1590x over previous
#include <cuda_runtime.h>
#include <cstdint>

// ============================================================
// BoneLinear: out = x @ (weight + w)^T
// Step 1: precompute Weff = weight + wblk@bone + bone (tf32 RNA) into g_weff
// Step 2: tf32 mma.sync GEMM [16384,4096] x [4096,4096]^T
// R9: kt-boundary sync hoisted off critical path; frag0-of-next-stage
//     prefetched under ks3's mma (no exposed stage-entry bubble)
// ============================================================

#define MDIM 16384
#define NDIM 4096
#define KDIM 4096

#define BM 128
#define BN 128
#define BK 32
#define STAGES 3
#define KT (KDIM / BK)        // 128
#define THREADS 128

// smem: 32 floats (128B) per row padded to 36 floats (144B) -> conflict-free
#define PITCH_F 36
#define PITCH_B (PITCH_F * 4)
#define A_STAGE_BYTES (BM * PITCH_B)   // 18432
#define B_STAGE_BYTES (BN * PITCH_B)   // 18432
#define STAGE_BYTES (A_STAGE_BYTES + B_STAGE_BYTES)  // 36864
#define SMEM_TOTAL (STAGES * STAGE_BYTES)            // 110592 (x2 CTAs = 221184)

__device__ float g_weff[(size_t)NDIM * KDIM];        // 64 MB

// ---------------- helpers ----------------
__device__ __forceinline__ uint32_t smem_u32(const void* p) {
    uint32_t a;
    asm("{ .reg .u64 t; cvta.to.shared.u64 t, %1; cvt.u32.u64 %0, t; }" : "=r"(a) : "l"(p));
    return a;
}
__device__ __forceinline__ void cp16(uint32_t sdst, const float* gsrc) {
    asm volatile("cp.async.cg.shared.global [%0], [%1], 16;" :: "r"(sdst), "l"(gsrc));
}
#define CP_COMMIT() asm volatile("cp.async.commit_group;" ::: "memory")
#define CP_WAIT1()  asm volatile("cp.async.wait_group 1;" ::: "memory")

__device__ __forceinline__ void ldmatrix4(uint32_t* r, uint32_t addr) {
    asm volatile("ldmatrix.sync.aligned.m8n8.x4.shared.b16 {%0,%1,%2,%3}, [%4];"
                 : "=r"(r[0]), "=r"(r[1]), "=r"(r[2]), "=r"(r[3]) : "r"(addr));
}
__device__ __forceinline__ uint32_t lds_b32(uint32_t addr) {
    uint32_t v;
    asm volatile("ld.shared.b32 %0, [%1];" : "=r"(v) : "r"(addr));
    return v;
}
__device__ __forceinline__ void mma_tf32(float* c, const uint32_t* a, const uint32_t* b) {
    asm volatile(
        "mma.sync.aligned.m16n8k8.row.col.f32.tf32.tf32.f32 "
        "{%0,%1,%2,%3}, {%4,%5,%6,%7}, {%8,%9}, {%0,%1,%2,%3};"
        : "+f"(c[0]), "+f"(c[1]), "+f"(c[2]), "+f"(c[3])
        : "r"(a[0]), "r"(a[1]), "r"(a[2]), "r"(a[3]), "r"(b[0]), "r"(b[1]));
}

// ---------------- precompute: Weff = weight + wblk@bone + bone (tf32 RNA) ----------------
__global__ void __launch_bounds__(256, 4)
bone_weff_kernel(const float* __restrict__ weight, const float* __restrict__ bone,
                 float* __restrict__ weff) {
    __shared__ float wT[64 * 65];   // wT[j*65+i] = W[i][j], pad 65 -> conflict-free
    __shared__ float bb[64 * 64];
    const int b = blockIdx.x, a = blockIdx.y;
    const int t = threadIdx.x;

    for (int idx = t; idx < 4096; idx += 256) {
        int i = idx >> 6, j = idx & 63;
        wT[j * 65 + i] = weight[(size_t)(a * 64 + i) * KDIM + b * 64 + j];
        bb[idx] = bone[(size_t)b * 4096 + idx];
    }
    __syncthreads();

    const int i = t >> 2;           // output row within block
    const int q = t & 3;            // quarter: cols q*16 .. q*16+15
    const int j0 = q * 16;

    float acc[16];
#pragma unroll
    for (int jj = 0; jj < 16; jj++)
        acc[jj] = wT[(j0 + jj) * 65 + i] + bb[i * 64 + j0 + jj];

    const float4* bb4 = reinterpret_cast<const float4*>(bb);
#pragma unroll 4
    for (int k = 0; k < 64; k++) {
        const float wv = wT[k * 65 + i];                 // 8 distinct banks/warp
        const float4 b0 = bb4[k * 16 + q * 4 + 0];       // broadcast LDS.128
        const float4 b1 = bb4[k * 16 + q * 4 + 1];
        const float4 b2 = bb4[k * 16 + q * 4 + 2];
        const float4 b3 = bb4[k * 16 + q * 4 + 3];
        acc[0] += wv * b0.x;  acc[1] += wv * b0.y;  acc[2] += wv * b0.z;  acc[3] += wv * b0.w;
        acc[4] += wv * b1.x;  acc[5] += wv * b1.y;  acc[6] += wv * b1.z;  acc[7] += wv * b1.w;
        acc[8] += wv * b2.x;  acc[9] += wv * b2.y;  acc[10] += wv * b2.z; acc[11] += wv * b2.w;
        acc[12] += wv * b3.x; acc[13] += wv * b3.y; acc[14] += wv * b3.z; acc[15] += wv * b3.w;
    }

#pragma unroll
    for (int jj = 0; jj < 16; jj++)
        asm("cvt.rna.tf32.f32 %0, %1;" : "=f"(acc[jj]) : "f"(acc[jj]));

    float* orow = weff + (size_t)(a * 64 + i) * KDIM + b * 64 + j0;
#pragma unroll
    for (int v = 0; v < 4; v++)
        *reinterpret_cast<float4*>(orow + v * 4) =
            make_float4(acc[v * 4], acc[v * 4 + 1], acc[v * 4 + 2], acc[v * 4 + 3]);
}

// ---------------- main GEMM kernel ----------------
__global__ void __launch_bounds__(THREADS, 2)
bone_gemm_kernel(const float* __restrict__ x, const float* __restrict__ weff,
                 float* __restrict__ out) {
    extern __shared__ __align__(128) char smem[];
    const uint32_t sb = smem_u32(smem);

    const int tid = threadIdx.x;
    const int wid = tid >> 5;
    const int lane = tid & 31;
    const int wm = wid & 1;        // 2 warps along M (64 rows each)
    const int wn = wid >> 1;       // 2 warps along N (64 cols each)
    const int bm = blockIdx.y * BM;
    const int bn = blockIdx.x * BN;

    // ---- cp.async: one quarter (2 A chunks + 2 B chunks per thread) ----
    auto issue_part = [&](int kt, int stage, int part) {
        const uint32_t as = sb + stage * STAGE_BYTES;
        const uint32_t bs = as + A_STAGE_BYTES;
        const int kcol = kt * BK;
#pragma unroll
        for (int j = part * 2; j < part * 2 + 2; j++) {
            int idx = tid + j * THREADS;
            int row = idx >> 3, seg = idx & 7;
            cp16(as + row * PITCH_B + seg * 16,
                 x + (size_t)(bm + row) * KDIM + kcol + seg * 4);
            cp16(bs + row * PITCH_B + seg * 16,
                 weff + (size_t)(bn + row) * KDIM + kcol + seg * 4);
        }
    };

    float c[4][8][4];
#pragma unroll
    for (int mt = 0; mt < 4; mt++)
#pragma unroll
        for (int nt = 0; nt < 8; nt++)
#pragma unroll
            for (int q = 0; q < 4; q++) c[mt][nt][q] = 0.0f;

    // per-lane smem offsets
    const uint32_t a_row = (uint32_t)(wm * 64 + (lane & 15));
    const uint32_t a_coff = (uint32_t)((lane >> 4) * 16);          // bytes within k
    const uint32_t b_row = (uint32_t)(wn * 64 + (lane >> 2));      // + nt*8
    const uint32_t b_koff = (uint32_t)((lane & 3) * 4);            // bytes

    // double-buffered fragments
    uint32_t af[2][4][4];
    uint32_t bf[2][8][2];

    auto load_frags = [&](int stage, int ks, int buf) {
        const uint32_t as = sb + stage * STAGE_BYTES;
        const uint32_t bs = as + A_STAGE_BYTES;
        const uint32_t k0b = (uint32_t)(ks * 32);  // 8 floats
#pragma unroll
        for (int mt = 0; mt < 4; mt++)
            ldmatrix4(af[buf][mt], as + (a_row + mt * 16) * PITCH_B + k0b + a_coff);
#pragma unroll
        for (int nt = 0; nt < 8; nt++) {
            uint32_t ba = bs + (b_row + nt * 8) * PITCH_B + k0b + b_koff;
            bf[buf][nt][0] = lds_b32(ba);
            bf[buf][nt][1] = lds_b32(ba + 16);
        }
    };

    // ---- prologue: stage0 full, stage1 full, stage2 part0 ----
#pragma unroll
    for (int p = 0; p < 4; p++) issue_part(0, 0, p);
    CP_COMMIT();
#pragma unroll
    for (int p = 0; p < 4; p++) issue_part(1, 1, p);
    CP_COMMIT();
    issue_part(2, 2, 0);

    CP_WAIT1();          // stage0 group complete
    __syncthreads();
    load_frags(0, 0, 0); // frag0 of kt=0 into buf0

    // ---- mainloop ----
    // per kt (consuming stage c=kt%3):
    //   ks0..ks2: load frag(ks+1) of c; mma(ks); issue part(ks+1) for kt+2
    //   at ks2: commit; wait1; syncthreads   (last smem read of c was frag3)
    //   ks3: load frag0 of kt+1 (stage ready); mma(3); issue part0 for kt+3
#pragma unroll 1
    for (int kt = 0; kt < KT; kt++) {
        const int f2 = (kt + 2) % STAGES;    // stage being refilled by parts 1-3
        const int f3 = (kt + 3) % STAGES;    // stage refill started at ks3
        const int cstage = kt % STAGES;
        const bool issue23 = (kt + 2) < KT;
        const bool issue3  = (kt + 3) < KT;

        // ks0
        load_frags(cstage, 1, 1);
#pragma unroll
        for (int mt = 0; mt < 4; mt++)
#pragma unroll
            for (int nt = 0; nt < 8; nt++) mma_tf32(c[mt][nt], af[0][mt], bf[0][nt]);
        if (issue23) issue_part(kt + 2, f2, 1);

        // ks1
        load_frags(cstage, 2, 0);
#pragma unroll
        for (int mt = 0; mt < 4; mt++)
#pragma unroll
            for (int nt = 0; nt < 8; nt++) mma_tf32(c[mt][nt], af[1][mt], bf[1][nt]);
        if (issue23) issue_part(kt + 2, f2, 2);

        // ks2 (last smem read of cstage is this frag load)
        load_frags(cstage, 3, 1);
#pragma unroll
        for (int mt = 0; mt < 4; mt++)
#pragma unroll
            for (int nt = 0; nt < 8; nt++) mma_tf32(c[mt][nt], af[0][mt], bf[0][nt]);
        if (issue23) issue_part(kt + 2, f2, 3);
        CP_COMMIT();
        CP_WAIT1();
        __syncthreads();

        // ks3 (overlap next-stage frag0 + refill part0 with this mma block)
        if (kt + 1 < KT) load_frags((kt + 1) % STAGES, 0, 0);
#pragma unroll
        for (int mt = 0; mt < 4; mt++)
#pragma unroll
            for (int nt = 0; nt < 8; nt++) mma_tf32(c[mt][nt], af[1][mt], bf[1][nt]);
        if (issue3) issue_part(kt + 3, f3, 0);
    }

    // ---- epilogue: fp32 stores ----
    const int er = bm + wm * 64 + (lane >> 2);
    const int ec = bn + wn * 64 + 2 * (lane & 3);
#pragma unroll
    for (int mt = 0; mt < 4; mt++) {
#pragma unroll
        for (int nt = 0; nt < 8; nt++) {
            float* p0 = out + (size_t)(er + mt * 16) * NDIM + ec + nt * 8;
            float* p1 = p0 + 8 * NDIM;
            *reinterpret_cast<float2*>(p0) = make_float2(c[mt][nt][0], c[mt][nt][1]);
            *reinterpret_cast<float2*>(p1) = make_float2(c[mt][nt][2], c[mt][nt][3]);
        }
    }
}

// ---------------- host ----------------
extern "C" void kernel_launch(void* const* d_in, const int* in_sizes, int n_in,
                              void* d_out, int out_size) {
    (void)in_sizes; (void)n_in; (void)out_size;
    const float* x      = (const float*)d_in[0];
    const float* weight = (const float*)d_in[1];
    const float* bone   = (const float*)d_in[2];
    float* out          = (float*)d_out;

    void* weff_ptr = nullptr;
    cudaGetSymbolAddress(&weff_ptr, g_weff);

    cudaFuncSetAttribute((const void*)bone_gemm_kernel,
                         cudaFuncAttributeMaxDynamicSharedMemorySize, SMEM_TOTAL);

    bone_weff_kernel<<<dim3(64, 64), 256>>>(weight, bone, (float*)weff_ptr);
    bone_gemm_kernel<<<dim3(NDIM / BN, MDIM / BM), THREADS, SMEM_TOTAL>>>(
        x, (const float*)weff_ptr, out);
}

// round 10
// speedup vs baseline: 1.8500x; 1.0769x over previous
#include <cuda_runtime.h>
#include <cstdint>

// ============================================================
// BoneLinear: out = x @ (weight + w)^T
// Step 1: precompute Weff = weight + wblk@bone + bone (tf32 RNA) into g_weff
//         R10: outer-product 4x4 micro-tile, 2 LDS.128/k, occ 5 (latency fix)
// Step 2: tf32 mma.sync GEMM [16384,4096] x [4096,4096]^T (frozen from R9)
// ============================================================

#define MDIM 16384
#define NDIM 4096
#define KDIM 4096

#define BM 128
#define BN 128
#define BK 32
#define STAGES 3
#define KT (KDIM / BK)        // 128
#define THREADS 128

// smem: 32 floats (128B) per row padded to 36 floats (144B) -> conflict-free
#define PITCH_F 36
#define PITCH_B (PITCH_F * 4)
#define A_STAGE_BYTES (BM * PITCH_B)   // 18432
#define B_STAGE_BYTES (BN * PITCH_B)   // 18432
#define STAGE_BYTES (A_STAGE_BYTES + B_STAGE_BYTES)  // 36864
#define SMEM_TOTAL (STAGES * STAGE_BYTES)            // 110592 (x2 CTAs = 221184)

__device__ float g_weff[(size_t)NDIM * KDIM];        // 64 MB

// ---------------- helpers ----------------
__device__ __forceinline__ uint32_t smem_u32(const void* p) {
    uint32_t a;
    asm("{ .reg .u64 t; cvta.to.shared.u64 t, %1; cvt.u32.u64 %0, t; }" : "=r"(a) : "l"(p));
    return a;
}
__device__ __forceinline__ void cp16(uint32_t sdst, const float* gsrc) {
    asm volatile("cp.async.cg.shared.global [%0], [%1], 16;" :: "r"(sdst), "l"(gsrc));
}
#define CP_COMMIT() asm volatile("cp.async.commit_group;" ::: "memory")
#define CP_WAIT1()  asm volatile("cp.async.wait_group 1;" ::: "memory")

__device__ __forceinline__ void ldmatrix4(uint32_t* r, uint32_t addr) {
    asm volatile("ldmatrix.sync.aligned.m8n8.x4.shared.b16 {%0,%1,%2,%3}, [%4];"
                 : "=r"(r[0]), "=r"(r[1]), "=r"(r[2]), "=r"(r[3]) : "r"(addr));
}
__device__ __forceinline__ uint32_t lds_b32(uint32_t addr) {
    uint32_t v;
    asm volatile("ld.shared.b32 %0, [%1];" : "=r"(v) : "r"(addr));
    return v;
}
__device__ __forceinline__ void mma_tf32(float* c, const uint32_t* a, const uint32_t* b) {
    asm volatile(
        "mma.sync.aligned.m16n8k8.row.col.f32.tf32.tf32.f32 "
        "{%0,%1,%2,%3}, {%4,%5,%6,%7}, {%8,%9}, {%0,%1,%2,%3};"
        : "+f"(c[0]), "+f"(c[1]), "+f"(c[2]), "+f"(c[3])
        : "r"(a[0]), "r"(a[1]), "r"(a[2]), "r"(a[3]), "r"(b[0]), "r"(b[1]));
}

// ---------------- precompute: Weff = weight + wblk@bone + bone (tf32 RNA) ----------------
// Block (b, a): 64x64 output block. 256 threads = 16x16 grid of 4x4 micro-tiles.
// Per k: 2x LDS.128 (wT broadcast, bb) feeding a 4x4 outer product.
#define WT_PITCH 68   // floats; 272B, 16B-aligned float4 rows, conflict-free reads
__global__ void __launch_bounds__(256, 5)
bone_weff_kernel(const float* __restrict__ weight, const float* __restrict__ bone,
                 float* __restrict__ weff) {
    __shared__ float wT[64 * WT_PITCH];   // wT[k*68+i] = Wblk[i][k]
    __shared__ float bb[64 * 64];         // bb[k*64+j] = bone[b][k][j]
    const int b = blockIdx.x, a = blockIdx.y;
    const int t = threadIdx.x;

    for (int idx = t; idx < 4096; idx += 256) {
        int i = idx >> 6, k = idx & 63;   // consecutive t -> consecutive k (gmem coalesced)
        wT[k * WT_PITCH + i] = weight[(size_t)(a * 64 + i) * KDIM + b * 64 + k];
        bb[idx] = bone[(size_t)b * 4096 + idx];
    }
    __syncthreads();

    const int ti = t >> 4;    // 0..15 -> rows i0 = ti*4
    const int tj = t & 15;    // 0..15 -> cols j0 = tj*4
    const int i0 = ti * 4, j0 = tj * 4;

    float acc[4][4];
    // init: W[i][j] + bone[i][j]   (W[i][j] = wT[j*68+i], scattered scalar reads; once)
#pragma unroll
    for (int r = 0; r < 4; r++)
#pragma unroll
        for (int cc = 0; cc < 4; cc++)
            acc[r][cc] = wT[(j0 + cc) * WT_PITCH + (i0 + r)] + bb[(i0 + r) * 64 + j0 + cc];

    const float4* wT4 = reinterpret_cast<const float4*>(wT);
    const float4* bb4 = reinterpret_cast<const float4*>(bb);
#pragma unroll 4
    for (int k = 0; k < 64; k++) {
        const float4 wv = wT4[k * (WT_PITCH / 4) + ti];  // W[i0..i0+3][k]
        const float4 bv = bb4[k * 16 + tj];              // bone[k][j0..j0+3]
        acc[0][0] += wv.x * bv.x; acc[0][1] += wv.x * bv.y; acc[0][2] += wv.x * bv.z; acc[0][3] += wv.x * bv.w;
        acc[1][0] += wv.y * bv.x; acc[1][1] += wv.y * bv.y; acc[1][2] += wv.y * bv.z; acc[1][3] += wv.y * bv.w;
        acc[2][0] += wv.z * bv.x; acc[2][1] += wv.z * bv.y; acc[2][2] += wv.z * bv.z; acc[2][3] += wv.z * bv.w;
        acc[3][0] += wv.w * bv.x; acc[3][1] += wv.w * bv.y; acc[3][2] += wv.w * bv.z; acc[3][3] += wv.w * bv.w;
    }

#pragma unroll
    for (int r = 0; r < 4; r++) {
#pragma unroll
        for (int cc = 0; cc < 4; cc++)
            asm("cvt.rna.tf32.f32 %0, %1;" : "=f"(acc[r][cc]) : "f"(acc[r][cc]));
        *reinterpret_cast<float4*>(
            weff + (size_t)(a * 64 + i0 + r) * KDIM + b * 64 + j0) =
            make_float4(acc[r][0], acc[r][1], acc[r][2], acc[r][3]);
    }
}

// ---------------- main GEMM kernel (frozen from R9) ----------------
__global__ void __launch_bounds__(THREADS, 2)
bone_gemm_kernel(const float* __restrict__ x, const float* __restrict__ weff,
                 float* __restrict__ out) {
    extern __shared__ __align__(128) char smem[];
    const uint32_t sb = smem_u32(smem);

    const int tid = threadIdx.x;
    const int wid = tid >> 5;
    const int lane = tid & 31;
    const int wm = wid & 1;        // 2 warps along M (64 rows each)
    const int wn = wid >> 1;       // 2 warps along N (64 cols each)
    const int bm = blockIdx.y * BM;
    const int bn = blockIdx.x * BN;

    // ---- cp.async: one quarter (2 A chunks + 2 B chunks per thread) ----
    auto issue_part = [&](int kt, int stage, int part) {
        const uint32_t as = sb + stage * STAGE_BYTES;
        const uint32_t bs = as + A_STAGE_BYTES;
        const int kcol = kt * BK;
#pragma unroll
        for (int j = part * 2; j < part * 2 + 2; j++) {
            int idx = tid + j * THREADS;
            int row = idx >> 3, seg = idx & 7;
            cp16(as + row * PITCH_B + seg * 16,
                 x + (size_t)(bm + row) * KDIM + kcol + seg * 4);
            cp16(bs + row * PITCH_B + seg * 16,
                 weff + (size_t)(bn + row) * KDIM + kcol + seg * 4);
        }
    };

    float c[4][8][4];
#pragma unroll
    for (int mt = 0; mt < 4; mt++)
#pragma unroll
        for (int nt = 0; nt < 8; nt++)
#pragma unroll
            for (int q = 0; q < 4; q++) c[mt][nt][q] = 0.0f;

    // per-lane smem offsets
    const uint32_t a_row = (uint32_t)(wm * 64 + (lane & 15));
    const uint32_t a_coff = (uint32_t)((lane >> 4) * 16);          // bytes within k
    const uint32_t b_row = (uint32_t)(wn * 64 + (lane >> 2));      // + nt*8
    const uint32_t b_koff = (uint32_t)((lane & 3) * 4);            // bytes

    // double-buffered fragments
    uint32_t af[2][4][4];
    uint32_t bf[2][8][2];

    auto load_frags = [&](int stage, int ks, int buf) {
        const uint32_t as = sb + stage * STAGE_BYTES;
        const uint32_t bs = as + A_STAGE_BYTES;
        const uint32_t k0b = (uint32_t)(ks * 32);  // 8 floats
#pragma unroll
        for (int mt = 0; mt < 4; mt++)
            ldmatrix4(af[buf][mt], as + (a_row + mt * 16) * PITCH_B + k0b + a_coff);
#pragma unroll
        for (int nt = 0; nt < 8; nt++) {
            uint32_t ba = bs + (b_row + nt * 8) * PITCH_B + k0b + b_koff;
            bf[buf][nt][0] = lds_b32(ba);
            bf[buf][nt][1] = lds_b32(ba + 16);
        }
    };

    // ---- prologue: stage0 full, stage1 full, stage2 part0 ----
#pragma unroll
    for (int p = 0; p < 4; p++) issue_part(0, 0, p);
    CP_COMMIT();
#pragma unroll
    for (int p = 0; p < 4; p++) issue_part(1, 1, p);
    CP_COMMIT();
    issue_part(2, 2, 0);

    CP_WAIT1();          // stage0 group complete
    __syncthreads();
    load_frags(0, 0, 0); // frag0 of kt=0 into buf0

    // ---- mainloop ----
#pragma unroll 1
    for (int kt = 0; kt < KT; kt++) {
        const int f2 = (kt + 2) % STAGES;    // stage being refilled by parts 1-3
        const int f3 = (kt + 3) % STAGES;    // stage refill started at ks3
        const int cstage = kt % STAGES;
        const bool issue23 = (kt + 2) < KT;
        const bool issue3  = (kt + 3) < KT;

        // ks0
        load_frags(cstage, 1, 1);
#pragma unroll
        for (int mt = 0; mt < 4; mt++)
#pragma unroll
            for (int nt = 0; nt < 8; nt++) mma_tf32(c[mt][nt], af[0][mt], bf[0][nt]);
        if (issue23) issue_part(kt + 2, f2, 1);

        // ks1
        load_frags(cstage, 2, 0);
#pragma unroll
        for (int mt = 0; mt < 4; mt++)
#pragma unroll
            for (int nt = 0; nt < 8; nt++) mma_tf32(c[mt][nt], af[1][mt], bf[1][nt]);
        if (issue23) issue_part(kt + 2, f2, 2);

        // ks2 (last smem read of cstage is this frag load)
        load_frags(cstage, 3, 1);
#pragma unroll
        for (int mt = 0; mt < 4; mt++)
#pragma unroll
            for (int nt = 0; nt < 8; nt++) mma_tf32(c[mt][nt], af[0][mt], bf[0][nt]);
        if (issue23) issue_part(kt + 2, f2, 3);
        CP_COMMIT();
        CP_WAIT1();
        __syncthreads();

        // ks3 (overlap next-stage frag0 + refill part0 with this mma block)
        if (kt + 1 < KT) load_frags((kt + 1) % STAGES, 0, 0);
#pragma unroll
        for (int mt = 0; mt < 4; mt++)
#pragma unroll
            for (int nt = 0; nt < 8; nt++) mma_tf32(c[mt][nt], af[1][mt], bf[1][nt]);
        if (issue3) issue_part(kt + 3, f3, 0);
    }

    // ---- epilogue: fp32 stores ----
    const int er = bm + wm * 64 + (lane >> 2);
    const int ec = bn + wn * 64 + 2 * (lane & 3);
#pragma unroll
    for (int mt = 0; mt < 4; mt++) {
#pragma unroll
        for (int nt = 0; nt < 8; nt++) {
            float* p0 = out + (size_t)(er + mt * 16) * NDIM + ec + nt * 8;
            float* p1 = p0 + 8 * NDIM;
            *reinterpret_cast<float2*>(p0) = make_float2(c[mt][nt][0], c[mt][nt][1]);
            *reinterpret_cast<float2*>(p1) = make_float2(c[mt][nt][2], c[mt][nt][3]);
        }
    }
}

// ---------------- host ----------------
extern "C" void kernel_launch(void* const* d_in, const int* in_sizes, int n_in,
                              void* d_out, int out_size) {
    (void)in_sizes; (void)n_in; (void)out_size;
    const float* x      = (const float*)d_in[0];
    const float* weight = (const float*)d_in[1];
    const float* bone   = (const float*)d_in[2];
    float* out          = (float*)d_out;

    void* weff_ptr = nullptr;
    cudaGetSymbolAddress(&weff_ptr, g_weff);

    cudaFuncSetAttribute((const void*)bone_gemm_kernel,
                         cudaFuncAttributeMaxDynamicSharedMemorySize, SMEM_TOTAL);

    bone_weff_kernel<<<dim3(64, 64), 256>>>(weight, bone, (float*)weff_ptr);
    bone_gemm_kernel<<<dim3(NDIM / BN, MDIM / BM), THREADS, SMEM_TOTAL>>>(
        x, (const float*)weff_ptr, out);
}